// round 4
// baseline (speedup 1.0000x reference)
#include <cuda_runtime.h>
#include <cuda_bf16.h>

// Problem constants: B=4, C=5, H=64, W=64, N=4096
#define BB 4
#define CC 5
#define WW 64
#define HW 4096
#define BSTRIDE 20480      // C*HW
#define NMAX 4096
#define M_TILE 8
#define LOG2E 1.4426950408889634f
#define KVBLKS 128         // kv blocks in prep (128 threads each)
#define PARTS_PER_B 32     // KVBLKS / BB

typedef unsigned long long u64;

// -------- scratch (device globals; no allocation allowed) --------
__device__ float g_kf[BB * CC * HW];
__device__ float g_vf[BB * CC * HW];
__device__ float g_q[NMAX * CC];        // log2(e)-scaled query projections
__device__ int   g_perm[NMAX];
__device__ int   g_off[BB + 1];
__device__ int   g_blkoff[BB + 1];
__device__ float g_pmin[KVBLKS][CC];
__device__ float g_pmax[KVBLKS][CC];
__device__ float g_pnrm[KVBLKS];

__device__ __forceinline__ float ex2f(float x) {
    float r; asm("ex2.approx.f32 %0, %1;" : "=f"(r) : "f"(x)); return r;
}
__device__ __forceinline__ u64 pack2(float lo, float hi) {
    u64 r; asm("mov.b64 %0, {%1,%2};" : "=l"(r) : "f"(lo), "f"(hi)); return r;
}
__device__ __forceinline__ void unpack2(u64 v, float& lo, float& hi) {
    asm("mov.b64 {%0,%1}, %2;" : "=f"(lo), "=f"(hi) : "l"(v));
}
__device__ __forceinline__ u64 fma2(u64 a, u64 b, u64 c) {
    u64 d; asm("fma.rn.f32x2 %0, %1, %2, %3;" : "=l"(d) : "l"(a), "l"(b), "l"(c)); return d;
}
__device__ __forceinline__ u64 add2(u64 a, u64 b) {
    u64 d; asm("add.rn.f32x2 %0, %1, %2;" : "=l"(d) : "l"(a), "l"(b)); return d;
}

// ---------------------------------------------------------------
// Kernel 1 (fused), 128 threads/block:
//   blocks [0,128)            : k/v projection + y=x copy + per-block k stats
//   blocks [128,128+qblocks)  : q projection (log2-scaled)
//   last block                : deterministic rank-based sort by batch + block offsets
// ---------------------------------------------------------------
__global__ void prep_kernel(const float* __restrict__ x,
                            const float* __restrict__ qw, const float* __restrict__ qb,
                            const float* __restrict__ kw, const float* __restrict__ kb,
                            const float* __restrict__ vw, const float* __restrict__ vb,
                            const int* __restrict__ ib, const int* __restrict__ ih,
                            const int* __restrict__ iw, int n,
                            float* __restrict__ y) {
    int tid = threadIdx.x;
    if (blockIdx.x < KVBLKS) {
        __shared__ float skw[25], skb[5], svw[25], svb[5];
        __shared__ float smin[4][CC], smax[4][CC], snrm[4];
        if (tid < 25) { skw[tid] = kw[tid]; svw[tid] = vw[tid]; }
        if (tid < 5)  { skb[tid] = kb[tid]; svb[tid] = vb[tid]; }
        __syncthreads();

        int t = blockIdx.x * 128 + tid;
        int b = t >> 12;
        int p = t & (HW - 1);
        const float* xb = x + b * BSTRIDE + p;
        float* yb = y + b * BSTRIDE + p;

        float xs[CC];
#pragma unroll
        for (int c = 0; c < CC; c++) { xs[c] = xb[c * HW]; yb[c * HW] = xs[c]; }

        float kk[CC]; float nrm = 0.0f;
#pragma unroll
        for (int o = 0; o < CC; o++) {
            float k = skb[o], v = svb[o];
#pragma unroll
            for (int c = 0; c < CC; c++) {
                k = fmaf(skw[o * CC + c], xs[c], k);
                v = fmaf(svw[o * CC + c], xs[c], v);
            }
            g_kf[b * BSTRIDE + o * HW + p] = k;
            g_vf[b * BSTRIDE + o * HW + p] = v;
            kk[o] = k;
            nrm = fmaf(k, k, nrm);
        }

        float mn[CC], mx[CC];
#pragma unroll
        for (int c = 0; c < CC; c++) { mn[c] = kk[c]; mx[c] = kk[c]; }
#pragma unroll
        for (int off = 16; off > 0; off >>= 1) {
#pragma unroll
            for (int c = 0; c < CC; c++) {
                mn[c] = fminf(mn[c], __shfl_xor_sync(0xffffffffu, mn[c], off));
                mx[c] = fmaxf(mx[c], __shfl_xor_sync(0xffffffffu, mx[c], off));
            }
            nrm = fmaxf(nrm, __shfl_xor_sync(0xffffffffu, nrm, off));
        }
        int wid = tid >> 5, lane = tid & 31;
        if (lane == 0) {
#pragma unroll
            for (int c = 0; c < CC; c++) { smin[wid][c] = mn[c]; smax[wid][c] = mx[c]; }
            snrm[wid] = nrm;
        }
        __syncthreads();
        if (tid < CC) {
            float a = smin[0][tid], bx = smax[0][tid];
#pragma unroll
            for (int w = 1; w < 4; w++) { a = fminf(a, smin[w][tid]); bx = fmaxf(bx, smax[w][tid]); }
            g_pmin[blockIdx.x][tid] = a;
            g_pmax[blockIdx.x][tid] = bx;
        }
        if (tid == CC) {
            float a = snrm[0];
#pragma unroll
            for (int w = 1; w < 4; w++) a = fmaxf(a, snrm[w]);
            g_pnrm[blockIdx.x] = a;
        }
    } else if (blockIdx.x < gridDim.x - 1) {
        __shared__ float sw[25], sb[5];
        if (tid < 25) sw[tid] = qw[tid];
        if (tid < 5)  sb[tid] = qb[tid];
        __syncthreads();
        int i = (blockIdx.x - KVBLKS) * 128 + tid;
        if (i >= n) return;
        int b = ib[i];
        int pix = ih[i] * WW + iw[i];
        const float* xb = x + b * BSTRIDE + pix;
        float xs[CC];
#pragma unroll
        for (int c = 0; c < CC; c++) xs[c] = xb[c * HW];
#pragma unroll
        for (int o = 0; o < CC; o++) {
            float q = sb[o];
#pragma unroll
            for (int c = 0; c < CC; c++) q = fmaf(sw[o * CC + c], xs[c], q);
            g_q[i * CC + o] = q * LOG2E;
        }
    } else {
        // deterministic rank-based counting sort by batch (atomic-free)
        __shared__ int s_cnt[128][BB];
        __shared__ int s_tot[BB], s_base[BB];
        int c0 = 0, c1 = 0, c2 = 0, c3 = 0;
        for (int i = tid; i < n; i += 128) {
            int b = ib[i];
            c0 += (b == 0); c1 += (b == 1); c2 += (b == 2); c3 += (b == 3);
        }
        s_cnt[tid][0] = c0; s_cnt[tid][1] = c1; s_cnt[tid][2] = c2; s_cnt[tid][3] = c3;
        __syncthreads();
        if (tid < BB) {
            int run = 0;
            for (int j = 0; j < 128; j++) { int t = s_cnt[j][tid]; s_cnt[j][tid] = run; run += t; }
            s_tot[tid] = run;
        }
        __syncthreads();
        if (tid == 0) {
            int acc = 0, bacc = 0;
            for (int b = 0; b < BB; b++) {
                g_off[b] = acc; s_base[b] = acc; acc += s_tot[b];
                g_blkoff[b] = bacc; bacc += (s_tot[b] + M_TILE - 1) / M_TILE;
            }
            g_off[BB] = acc;
            g_blkoff[BB] = bacc;
        }
        __syncthreads();
        int cur[BB];
#pragma unroll
        for (int b = 0; b < BB; b++) cur[b] = s_base[b] + s_cnt[tid][b];
        for (int i = tid; i < n; i += 128) {
            int b = ib[i];
            g_perm[cur[b]++] = i;
        }
    }
}

// ---------------------------------------------------------------
// Kernel 2: one-pass bounded-softmax attention, guard-free, packed f32x2.
// lmax = min(separable, Cauchy) true upper bound - 32 (log2 units),
// block-uniform per m -> no guard, no max alignment, plain sums.
// 1D exact grid; one block = M_TILE queries of one batch.
// ---------------------------------------------------------------
__global__ void __launch_bounds__(256, 1)
attn_kernel(const float* __restrict__ x,
            const int* __restrict__ ih, const int* __restrict__ iw,
            const float* __restrict__ gamma, float* __restrict__ y) {
    int tid = threadIdx.x;

    __shared__ int   s_boff[BB + 1], s_off[BB + 1];
    __shared__ int   s_n[M_TILE];
    __shared__ float s_kmn[CC], s_kmx[CC], s_knrm;
    __shared__ float s_red[M_TILE * 6 * 8];

    if (tid < BB + 1) { s_boff[tid] = g_blkoff[tid]; s_off[tid] = g_off[tid]; }
    __syncthreads();

    int blk = blockIdx.x;
    if (blk >= s_boff[BB]) return;
    int b = 0;
    while (blk >= s_boff[b + 1]) b++;
    int base = s_off[b] + (blk - s_boff[b]) * M_TILE;
    int end = s_off[b + 1];
    int mcnt = min(M_TILE, end - base);

    if (tid < M_TILE) s_n[tid] = (tid < mcnt) ? g_perm[base + tid] : -1;
    // finalize per-batch k stats from PARTS_PER_B partials
    if (tid >= 32 && tid < 32 + CC) {
        int c = tid - 32;
        float a = 3.0e38f;
#pragma unroll
        for (int k = 0; k < PARTS_PER_B; k++) a = fminf(a, g_pmin[b * PARTS_PER_B + k][c]);
        s_kmn[c] = a;
    } else if (tid >= 64 && tid < 64 + CC) {
        int c = tid - 64;
        float a = -3.0e38f;
#pragma unroll
        for (int k = 0; k < PARTS_PER_B; k++) a = fmaxf(a, g_pmax[b * PARTS_PER_B + k][c]);
        s_kmx[c] = a;
    } else if (tid == 96) {
        float a = 0.0f;
#pragma unroll
        for (int k = 0; k < PARTS_PER_B; k++) a = fmaxf(a, g_pnrm[b * PARTS_PER_B + k]);
        s_knrm = sqrtf(a);
    }
    __syncthreads();

    // packed (q,q) per m,c and packed bound seed
    u64 q2[M_TILE][CC];
    u64 nl2[M_TILE];
    {
        float knrm = s_knrm;
#pragma unroll
        for (int m = 0; m < M_TILE; m++) {
            int nq = s_n[m];
            float qs[CC];
            float sep = 0.0f, qq = 0.0f;
#pragma unroll
            for (int c = 0; c < CC; c++) {
                float v = (nq >= 0) ? __ldg(&g_q[nq * CC + c]) : 0.0f;
                qs[c] = v;
                q2[m][c] = pack2(v, v);
                sep += fmaxf(v * s_kmx[c], v * s_kmn[c]);
                qq = fmaf(v, v, qq);
            }
            float cau = sqrtf(qq) * knrm;
            float nl = 32.0f - fminf(sep, cau);
            nl2[m] = pack2(nl, nl);
        }
    }

    const u64* kf2 = (const u64*)g_kf + b * (BSTRIDE / 2);
    const u64* vf2 = (const u64*)g_vf + b * (BSTRIDE / 2);

    u64 ssum2[M_TILE];
    u64 oacc2[M_TILE][CC];
#pragma unroll
    for (int m = 0; m < M_TILE; m++) {
        ssum2[m] = 0ull;
#pragma unroll
        for (int c = 0; c < CC; c++) oacc2[m][c] = 0ull;
    }

#pragma unroll 1
    for (int it = 0; it < 8; it++) {
        int p2 = tid + it * 256;           // u64 index, 2048 per channel
        u64 k0 = kf2[p2];
        u64 k1 = kf2[2048 + p2];
        u64 k2 = kf2[2 * 2048 + p2];
        u64 k3 = kf2[3 * 2048 + p2];
        u64 k4 = kf2[4 * 2048 + p2];
        u64 v0 = vf2[p2];
        u64 v1 = vf2[2048 + p2];
        u64 v2 = vf2[2 * 2048 + p2];
        u64 v3 = vf2[3 * 2048 + p2];
        u64 v4 = vf2[4 * 2048 + p2];
#pragma unroll
        for (int m = 0; m < M_TILE; m++) {
            u64 e2 = fma2(q2[m][0], k0, nl2[m]);
            e2 = fma2(q2[m][1], k1, e2);
            e2 = fma2(q2[m][2], k2, e2);
            e2 = fma2(q2[m][3], k3, e2);
            e2 = fma2(q2[m][4], k4, e2);
            float ex, ey;
            unpack2(e2, ex, ey);
            float wx = ex2f(ex);
            float wy = ex2f(ey);
            u64 w2 = pack2(wx, wy);
            ssum2[m] = add2(ssum2[m], w2);
            oacc2[m][0] = fma2(w2, v0, oacc2[m][0]);
            oacc2[m][1] = fma2(w2, v1, oacc2[m][1]);
            oacc2[m][2] = fma2(w2, v2, oacc2[m][2]);
            oacc2[m][3] = fma2(w2, v3, oacc2[m][3]);
            oacc2[m][4] = fma2(w2, v4, oacc2[m][4]);
        }
    }

    // collapse packed halves to scalars
    float ssum[M_TILE];
    float oacc[M_TILE][CC];
#pragma unroll
    for (int m = 0; m < M_TILE; m++) {
        float lo, hi;
        unpack2(ssum2[m], lo, hi);
        ssum[m] = lo + hi;
#pragma unroll
        for (int c = 0; c < CC; c++) {
            unpack2(oacc2[m][c], lo, hi);
            oacc[m][c] = lo + hi;
        }
    }

    int wid = tid >> 5, lane = tid & 31;

    // ---- sum reduction (bound uniform -> plain sums) ----
#pragma unroll
    for (int m = 0; m < M_TILE; m++) {
#pragma unroll
        for (int off = 16; off > 0; off >>= 1)
            ssum[m] += __shfl_xor_sync(0xffffffffu, ssum[m], off);
#pragma unroll
        for (int c = 0; c < CC; c++) {
#pragma unroll
            for (int off = 16; off > 0; off >>= 1)
                oacc[m][c] += __shfl_xor_sync(0xffffffffu, oacc[m][c], off);
        }
    }
    if (lane == 0) {
#pragma unroll
        for (int m = 0; m < M_TILE; m++) {
            s_red[(m * 6 + 0) * 8 + wid] = ssum[m];
#pragma unroll
            for (int c = 0; c < CC; c++)
                s_red[(m * 6 + 1 + c) * 8 + wid] = oacc[m][c];
        }
    }
    __syncthreads();

    if (tid < mcnt) {
        int m = tid;
        float s = 0.0f;
#pragma unroll
        for (int w = 0; w < 8; w++) s += s_red[(m * 6) * 8 + w];
        float inv = 1.0f / s;
        float g = gamma[0];
        int nq = s_n[m];
        int pix = ih[nq] * WW + iw[nq];
#pragma unroll
        for (int c = 0; c < CC; c++) {
            float oc = 0.0f;
#pragma unroll
            for (int w = 0; w < 8; w++) oc += s_red[(m * 6 + 1 + c) * 8 + w];
            int idx = b * BSTRIDE + c * HW + pix;
            y[idx] = fmaf(g, oc * inv, x[idx]);
        }
    }
}

// ---------------------------------------------------------------
// launch
// ---------------------------------------------------------------
extern "C" void kernel_launch(void* const* d_in, const int* in_sizes, int n_in,
                              void* d_out, int out_size) {
    const float* x     = (const float*)d_in[0];
    const float* qw    = (const float*)d_in[2];
    const float* qb    = (const float*)d_in[3];
    const float* kw    = (const float*)d_in[4];
    const float* kb    = (const float*)d_in[5];
    const float* vw    = (const float*)d_in[6];
    const float* vb    = (const float*)d_in[7];
    const float* gamma = (const float*)d_in[8];
    const int*   ib    = (const int*)d_in[9];
    const int*   ih    = (const int*)d_in[10];
    const int*   iw    = (const int*)d_in[11];
    float* y = (float*)d_out;

    int n = in_sizes[9];
    int qblocks = (n + 127) / 128;

    prep_kernel<<<KVBLKS + qblocks + 1, 128>>>(x, qw, qb, kw, kb, vw, vb, ib, ih, iw, n, y);

    int maxblk = (n + M_TILE - 1) / M_TILE + BB - 1;   // exact upper bound on working blocks
    attn_kernel<<<maxblk, 256>>>(x, ih, iw, gamma, y);
}

// round 6
// speedup vs baseline: 1.4006x; 1.4006x over previous
#include <cuda_runtime.h>
#include <cuda_bf16.h>

// Problem constants: B=4, C=5, H=64, W=64, N=4096
#define BB 4
#define CC 5
#define WW 64
#define HW 4096
#define BSTRIDE 20480      // C*HW
#define NMAX 4096
#define M_TILE 4
#define LOG2E 1.4426950408889634f
#define KVBLKS 128         // kv blocks in prep (128 threads each)
#define PARTS_PER_B 32     // KVBLKS / BB

// -------- scratch (device globals; no allocation allowed) --------
__device__ float g_kf[BB * CC * HW];
__device__ float g_vf[BB * CC * HW];
__device__ float g_q[NMAX * CC];        // log2(e)-scaled query projections
__device__ int   g_perm[NMAX];
__device__ int   g_off[BB + 1];
__device__ int   g_blkoff[BB + 1];
__device__ float g_pmin[KVBLKS][CC];
__device__ float g_pmax[KVBLKS][CC];
__device__ float g_pnrm[KVBLKS];

__device__ __forceinline__ float ex2f(float x) {
    float r; asm("ex2.approx.f32 %0, %1;" : "=f"(r) : "f"(x)); return r;
}

// ---------------------------------------------------------------
// Kernel 1 (fused), 128 threads/block:
//   blocks [0,128)            : k/v projection + y=x copy + per-block k stats
//   blocks [128,128+qblocks)  : q projection (log2-scaled)
//   last block                : deterministic rank-based sort by batch + block offsets
// ---------------------------------------------------------------
__global__ void prep_kernel(const float* __restrict__ x,
                            const float* __restrict__ qw, const float* __restrict__ qb,
                            const float* __restrict__ kw, const float* __restrict__ kb,
                            const float* __restrict__ vw, const float* __restrict__ vb,
                            const int* __restrict__ ib, const int* __restrict__ ih,
                            const int* __restrict__ iw, int n,
                            float* __restrict__ y) {
    int tid = threadIdx.x;
    if (blockIdx.x < KVBLKS) {
        __shared__ float skw[25], skb[5], svw[25], svb[5];
        __shared__ float smin[4][CC], smax[4][CC], snrm[4];
        if (tid < 25) { skw[tid] = kw[tid]; svw[tid] = vw[tid]; }
        if (tid < 5)  { skb[tid] = kb[tid]; svb[tid] = vb[tid]; }
        __syncthreads();

        int t = blockIdx.x * 128 + tid;
        int b = t >> 12;
        int p = t & (HW - 1);
        const float* xb = x + b * BSTRIDE + p;
        float* yb = y + b * BSTRIDE + p;

        float xs[CC];
#pragma unroll
        for (int c = 0; c < CC; c++) { xs[c] = xb[c * HW]; yb[c * HW] = xs[c]; }

        float kk[CC]; float nrm = 0.0f;
#pragma unroll
        for (int o = 0; o < CC; o++) {
            float k = skb[o], v = svb[o];
#pragma unroll
            for (int c = 0; c < CC; c++) {
                k = fmaf(skw[o * CC + c], xs[c], k);
                v = fmaf(svw[o * CC + c], xs[c], v);
            }
            g_kf[b * BSTRIDE + o * HW + p] = k;
            g_vf[b * BSTRIDE + o * HW + p] = v;
            kk[o] = k;
            nrm = fmaf(k, k, nrm);
        }

        float mn[CC], mx[CC];
#pragma unroll
        for (int c = 0; c < CC; c++) { mn[c] = kk[c]; mx[c] = kk[c]; }
#pragma unroll
        for (int off = 16; off > 0; off >>= 1) {
#pragma unroll
            for (int c = 0; c < CC; c++) {
                mn[c] = fminf(mn[c], __shfl_xor_sync(0xffffffffu, mn[c], off));
                mx[c] = fmaxf(mx[c], __shfl_xor_sync(0xffffffffu, mx[c], off));
            }
            nrm = fmaxf(nrm, __shfl_xor_sync(0xffffffffu, nrm, off));
        }
        int wid = tid >> 5, lane = tid & 31;
        if (lane == 0) {
#pragma unroll
            for (int c = 0; c < CC; c++) { smin[wid][c] = mn[c]; smax[wid][c] = mx[c]; }
            snrm[wid] = nrm;
        }
        __syncthreads();
        if (tid < CC) {
            float a = smin[0][tid], bx = smax[0][tid];
#pragma unroll
            for (int w = 1; w < 4; w++) { a = fminf(a, smin[w][tid]); bx = fmaxf(bx, smax[w][tid]); }
            g_pmin[blockIdx.x][tid] = a;
            g_pmax[blockIdx.x][tid] = bx;
        }
        if (tid == CC) {
            float a = snrm[0];
#pragma unroll
            for (int w = 1; w < 4; w++) a = fmaxf(a, snrm[w]);
            g_pnrm[blockIdx.x] = a;
        }
    } else if (blockIdx.x < gridDim.x - 1) {
        __shared__ float sw[25], sb[5];
        if (tid < 25) sw[tid] = qw[tid];
        if (tid < 5)  sb[tid] = qb[tid];
        __syncthreads();
        int i = (blockIdx.x - KVBLKS) * 128 + tid;
        if (i >= n) return;
        int b = ib[i];
        int pix = ih[i] * WW + iw[i];
        const float* xb = x + b * BSTRIDE + pix;
        float xs[CC];
#pragma unroll
        for (int c = 0; c < CC; c++) xs[c] = xb[c * HW];
#pragma unroll
        for (int o = 0; o < CC; o++) {
            float q = sb[o];
#pragma unroll
            for (int c = 0; c < CC; c++) q = fmaf(sw[o * CC + c], xs[c], q);
            g_q[i * CC + o] = q * LOG2E;
        }
    } else {
        // deterministic rank-based counting sort by batch (atomic-free)
        __shared__ int s_cnt[128][BB];
        __shared__ int s_tot[BB], s_base[BB];
        int c0 = 0, c1 = 0, c2 = 0, c3 = 0;
        for (int i = tid; i < n; i += 128) {
            int b = ib[i];
            c0 += (b == 0); c1 += (b == 1); c2 += (b == 2); c3 += (b == 3);
        }
        s_cnt[tid][0] = c0; s_cnt[tid][1] = c1; s_cnt[tid][2] = c2; s_cnt[tid][3] = c3;
        __syncthreads();
        if (tid < BB) {
            int run = 0;
            for (int j = 0; j < 128; j++) { int t = s_cnt[j][tid]; s_cnt[j][tid] = run; run += t; }
            s_tot[tid] = run;
        }
        __syncthreads();
        if (tid == 0) {
            int acc = 0, bacc = 0;
            for (int b = 0; b < BB; b++) {
                g_off[b] = acc; s_base[b] = acc; acc += s_tot[b];
                g_blkoff[b] = bacc; bacc += (s_tot[b] + M_TILE - 1) / M_TILE;
            }
            g_off[BB] = acc;
            g_blkoff[BB] = bacc;
        }
        __syncthreads();
        int cur[BB];
#pragma unroll
        for (int b = 0; b < BB; b++) cur[b] = s_base[b] + s_cnt[tid][b];
        for (int i = tid; i < n; i += 128) {
            int b = ib[i];
            g_perm[cur[b]++] = i;
        }
    }
}

// ---------------------------------------------------------------
// Kernel 2: one-pass bounded-softmax attention, guard-free, scalar FMA.
// M_TILE=4 queries per 128-thread block -> ~85-100 regs -> high occupancy.
// lmax = min(separable, Cauchy) true upper bound - 32 (log2 units),
// block-uniform per m -> no guard, no max alignment, plain sums.
// ---------------------------------------------------------------
__global__ void __launch_bounds__(128, 5)
attn_kernel(const float* __restrict__ x,
            const int* __restrict__ ih, const int* __restrict__ iw,
            const float* __restrict__ gamma, float* __restrict__ y) {
    int tid = threadIdx.x;

    __shared__ int   s_boff[BB + 1], s_off[BB + 1];
    __shared__ int   s_n[M_TILE];
    __shared__ float s_kmn[CC], s_kmx[CC], s_knrm;
    __shared__ float s_red[M_TILE * 6 * 4];

    if (tid < BB + 1) { s_boff[tid] = g_blkoff[tid]; s_off[tid] = g_off[tid]; }
    __syncthreads();

    int blk = blockIdx.x;
    if (blk >= s_boff[BB]) return;
    int b = 0;
    while (blk >= s_boff[b + 1]) b++;
    int base = s_off[b] + (blk - s_boff[b]) * M_TILE;
    int end = s_off[b + 1];
    int mcnt = min(M_TILE, end - base);

    if (tid < M_TILE) s_n[tid] = (tid < mcnt) ? g_perm[base + tid] : -1;
    // finalize per-batch k stats from PARTS_PER_B partials (cheap, per block)
    if (tid >= 32 && tid < 32 + CC) {
        int c = tid - 32;
        float a = 3.0e38f;
#pragma unroll
        for (int k = 0; k < PARTS_PER_B; k++) a = fminf(a, g_pmin[b * PARTS_PER_B + k][c]);
        s_kmn[c] = a;
    } else if (tid >= 64 && tid < 64 + CC) {
        int c = tid - 64;
        float a = -3.0e38f;
#pragma unroll
        for (int k = 0; k < PARTS_PER_B; k++) a = fmaxf(a, g_pmax[b * PARTS_PER_B + k][c]);
        s_kmx[c] = a;
    } else if (tid == 96) {
        float a = 0.0f;
#pragma unroll
        for (int k = 0; k < PARTS_PER_B; k++) a = fmaxf(a, g_pnrm[b * PARTS_PER_B + k]);
        s_knrm = sqrtf(a);
    }
    __syncthreads();

    float q[M_TILE][CC];
#pragma unroll
    for (int m = 0; m < M_TILE; m++) {
        int nq = s_n[m];
#pragma unroll
        for (int c = 0; c < CC; c++)
            q[m][c] = (nq >= 0) ? __ldg(&g_q[nq * CC + c]) : 0.0f;
    }

    // nlmax[m] = 32 - min(separable, Cauchy) upper bound (block-uniform)
    float nlmax[M_TILE];
    {
        float knrm = s_knrm;
#pragma unroll
        for (int m = 0; m < M_TILE; m++) {
            float sep = 0.0f, qq = 0.0f;
#pragma unroll
            for (int c = 0; c < CC; c++) {
                sep += fmaxf(q[m][c] * s_kmx[c], q[m][c] * s_kmn[c]);
                qq = fmaf(q[m][c], q[m][c], qq);
            }
            float cau = sqrtf(qq) * knrm;
            nlmax[m] = 32.0f - fminf(sep, cau);
        }
    }

    const float2* kf2 = (const float2*)(g_kf + b * BSTRIDE);
    const float2* vf2 = (const float2*)(g_vf + b * BSTRIDE);

    float ssum[M_TILE];
    float oacc[M_TILE][CC];
#pragma unroll
    for (int m = 0; m < M_TILE; m++) {
        ssum[m] = 0.0f;
#pragma unroll
        for (int c = 0; c < CC; c++) oacc[m][c] = 0.0f;
    }

#pragma unroll 1
    for (int it = 0; it < 16; it++) {
        int p2 = tid + it * 128;           // float2 index, 2048 per channel
        float2 k0 = kf2[p2];
        float2 k1 = kf2[2048 + p2];
        float2 k2 = kf2[2 * 2048 + p2];
        float2 k3 = kf2[3 * 2048 + p2];
        float2 k4 = kf2[4 * 2048 + p2];
        float2 v0 = vf2[p2];
        float2 v1 = vf2[2048 + p2];
        float2 v2 = vf2[2 * 2048 + p2];
        float2 v3 = vf2[3 * 2048 + p2];
        float2 v4 = vf2[4 * 2048 + p2];
#pragma unroll
        for (int m = 0; m < M_TILE; m++) {
            float ex = fmaf(q[m][0], k0.x, nlmax[m]);
            ex = fmaf(q[m][1], k1.x, ex);
            ex = fmaf(q[m][2], k2.x, ex);
            ex = fmaf(q[m][3], k3.x, ex);
            ex = fmaf(q[m][4], k4.x, ex);
            float ey = fmaf(q[m][0], k0.y, nlmax[m]);
            ey = fmaf(q[m][1], k1.y, ey);
            ey = fmaf(q[m][2], k2.y, ey);
            ey = fmaf(q[m][3], k3.y, ey);
            ey = fmaf(q[m][4], k4.y, ey);
            float wx = ex2f(ex);
            float wy = ex2f(ey);
            ssum[m] += wx + wy;
            oacc[m][0] = fmaf(wx, v0.x, fmaf(wy, v0.y, oacc[m][0]));
            oacc[m][1] = fmaf(wx, v1.x, fmaf(wy, v1.y, oacc[m][1]));
            oacc[m][2] = fmaf(wx, v2.x, fmaf(wy, v2.y, oacc[m][2]));
            oacc[m][3] = fmaf(wx, v3.x, fmaf(wy, v3.y, oacc[m][3]));
            oacc[m][4] = fmaf(wx, v4.x, fmaf(wy, v4.y, oacc[m][4]));
        }
    }

    int wid = tid >> 5, lane = tid & 31;

    // ---- sum reduction (bound uniform -> plain sums) ----
#pragma unroll
    for (int m = 0; m < M_TILE; m++) {
#pragma unroll
        for (int off = 16; off > 0; off >>= 1)
            ssum[m] += __shfl_xor_sync(0xffffffffu, ssum[m], off);
#pragma unroll
        for (int c = 0; c < CC; c++) {
#pragma unroll
            for (int off = 16; off > 0; off >>= 1)
                oacc[m][c] += __shfl_xor_sync(0xffffffffu, oacc[m][c], off);
        }
    }
    if (lane == 0) {
#pragma unroll
        for (int m = 0; m < M_TILE; m++) {
            s_red[(m * 6 + 0) * 4 + wid] = ssum[m];
#pragma unroll
            for (int c = 0; c < CC; c++)
                s_red[(m * 6 + 1 + c) * 4 + wid] = oacc[m][c];
        }
    }
    __syncthreads();

    if (tid < mcnt) {
        int m = tid;
        float s = 0.0f;
#pragma unroll
        for (int w = 0; w < 4; w++) s += s_red[(m * 6) * 4 + w];
        float inv = 1.0f / s;
        float g = gamma[0];
        int nq = s_n[m];
        int pix = ih[nq] * WW + iw[nq];
#pragma unroll
        for (int c = 0; c < CC; c++) {
            float oc = 0.0f;
#pragma unroll
            for (int w = 0; w < 4; w++) oc += s_red[(m * 6 + 1 + c) * 4 + w];
            int idx = b * BSTRIDE + c * HW + pix;
            y[idx] = fmaf(g, oc * inv, x[idx]);
        }
    }
}

// ---------------------------------------------------------------
// launch
// ---------------------------------------------------------------
extern "C" void kernel_launch(void* const* d_in, const int* in_sizes, int n_in,
                              void* d_out, int out_size) {
    const float* x     = (const float*)d_in[0];
    const float* qw    = (const float*)d_in[2];
    const float* qb    = (const float*)d_in[3];
    const float* kw    = (const float*)d_in[4];
    const float* kb    = (const float*)d_in[5];
    const float* vw    = (const float*)d_in[6];
    const float* vb    = (const float*)d_in[7];
    const float* gamma = (const float*)d_in[8];
    const int*   ib    = (const int*)d_in[9];
    const int*   ih    = (const int*)d_in[10];
    const int*   iw    = (const int*)d_in[11];
    float* y = (float*)d_out;

    int n = in_sizes[9];
    int qblocks = (n + 127) / 128;

    prep_kernel<<<KVBLKS + qblocks + 1, 128>>>(x, qw, qb, kw, kb, vw, vb, ib, ih, iw, n, y);

    int maxblk = (n + M_TILE - 1) / M_TILE + BB - 1;   // exact upper bound on working blocks
    attn_kernel<<<maxblk, 128>>>(x, ih, iw, gamma, y);
}